// round 2
// baseline (speedup 1.0000x reference)
#include <cuda_runtime.h>
#include <cstddef>

typedef unsigned long long ULL;

// 512 MB scratch for precomputed input-gate projections xg[b][t][g]
__device__ float g_xg[(size_t)128 * 2048 * 512];

__device__ __forceinline__ void fma2(ULL &acc, ULL a, ULL b) {
    asm("fma.rn.f32x2 %0, %1, %2, %0;" : "+l"(acc) : "l"(a), "l"(b));
}
__device__ __forceinline__ ULL dup2(float w) {
    ULL r; asm("mov.b64 %0, {%1, %1};" : "=l"(r) : "f"(w)); return r;
}
__device__ __forceinline__ float2 unpk(ULL u) {
    float2 v; asm("mov.b64 {%0, %1}, %2;" : "=f"(v.x), "=f"(v.y) : "l"(u)); return v;
}

// ---------------------------------------------------------------------------
// Phase 1: xg[b][t][g] = sum_i x[b,0,i,t] * W_ih[g,i] + (b_ih[g] + b_hh[g])
// Grid: (16 t-tiles, 2 gate-halves, 128 batch), 512 threads.
// smem: W half [256][129] fp32 (pad 129 -> conflict-free lane-g reads),
//       x tile  [128 i][32 float4-of-t] (warp-broadcast reads).
// ---------------------------------------------------------------------------
__global__ __launch_bounds__(512, 1)
void xg_kernel(const float* __restrict__ x, const float* __restrict__ W_ih,
               const float* __restrict__ b_ih, const float* __restrict__ b_hh)
{
    extern __shared__ float sm[];
    float* wsm = sm;                               // 256*129 floats = 132096 B
    float4* xs4 = (float4*)(sm + 256 * 129);       // 128*32 float4 = 65536 B

    const int tid   = threadIdx.x;
    const int b     = blockIdx.z;
    const int gBase = blockIdx.y * 256;
    const int t0    = blockIdx.x * 128;

    // load W_ih half into smem, layout wsm[g][i], row stride 129
    for (int idx = tid; idx < 256 * 128; idx += 512) {
        int i = idx & 127, g = idx >> 7;
        wsm[g * 129 + i] = W_ih[(size_t)(gBase + g) * 128 + i];
    }
    // load x tile: xs4[i][t4], t fastest in global -> coalesced float4
    const float4* x4 = (const float4*)x;
    size_t xbase = (size_t)b * 65536 + (size_t)(t0 >> 2);
    for (int idx = tid; idx < 128 * 32; idx += 512) {
        int t4 = idx & 31, i = idx >> 5;
        xs4[i * 32 + t4] = x4[xbase + (size_t)i * 512 + t4];
    }
    __syncthreads();

    const int gG = tid & 31;   // lane -> gate group (gates gG + 32*j)
    const int tG = tid >> 5;   // warp -> t group (8 t values)

    ULL acc[4][8];
    #pragma unroll
    for (int p = 0; p < 4; ++p)
        #pragma unroll
        for (int j = 0; j < 8; ++j) acc[p][j] = 0ULL;

    const ulonglong2* xu2 = (const ulonglong2*)xs4;

    #pragma unroll 4
    for (int k = 0; k < 128; ++k) {
        ulonglong2 xa = xu2[k * 32 + tG * 2];       // t pairs 0,1 (broadcast)
        ulonglong2 xb = xu2[k * 32 + tG * 2 + 1];   // t pairs 2,3
        #pragma unroll
        for (int j = 0; j < 8; ++j) {
            ULL wd = dup2(wsm[(gG + 32 * j) * 129 + k]);
            fma2(acc[0][j], wd, xa.x);
            fma2(acc[1][j], wd, xa.y);
            fma2(acc[2][j], wd, xb.x);
            fma2(acc[3][j], wd, xb.y);
        }
    }

    float bv[8];
    #pragma unroll
    for (int j = 0; j < 8; ++j) {
        int g = gBase + gG + 32 * j;
        bv[j] = b_ih[g] + b_hh[g];
    }

    #pragma unroll
    for (int p = 0; p < 4; ++p) {
        #pragma unroll
        for (int j = 0; j < 8; ++j) {
            float2 v = unpk(acc[p][j]);
            size_t r0 = ((size_t)b * 2048 + (size_t)(t0 + tG * 8 + 2 * p)) * 512
                        + gBase + gG + 32 * j;
            g_xg[r0]       = v.x + bv[j];   // coalesced across lanes (gG)
            g_xg[r0 + 512] = v.y + bv[j];
        }
    }
}

// ---------------------------------------------------------------------------
// Phase 2: persistent recurrence. 1 CTA per batch sample, 256 threads.
// Thread tid owns gate rows g0=tid (i/f block) and g1=tid+256 (g/o block).
// W_hh k in [0,64):  register-resident f32x2 pairs (128 regs/thread).
// W_hh k in [64,128): smem, pair-major [kp][512 gates] (conflict-free).
// h broadcast from smem via 16B loads. Head fused at the end.
// ---------------------------------------------------------------------------
__global__ __launch_bounds__(256, 1)
void lstm_rec_kernel(const float* __restrict__ W_hh,
                     const float* __restrict__ h0, const float* __restrict__ c0,
                     const float* __restrict__ W_out, const float* __restrict__ b_out,
                     const float* __restrict__ W_cls, const float* __restrict__ b_cls,
                     float* __restrict__ out)
{
    extern __shared__ ULL smB[];
    ULL*   wsm2 = smB;                        // [32][512] ULL = 131072 B
    float* hsm  = (float*)(wsm2 + 32 * 512);  // 128 floats (16B aligned)
    float* gsm  = hsm + 128;                  // 512 floats

    const int tid = threadIdx.x;
    const int b   = blockIdx.x;
    const int g0  = tid;
    const int g1  = tid + 256;

    const ULL* Wu = (const ULL*)W_hh;  // [512 gates][64 k-pairs]

    ULL w0p[32], w1p[32];
    #pragma unroll
    for (int kp = 0; kp < 32; ++kp) w0p[kp] = Wu[(size_t)g0 * 64 + kp];
    #pragma unroll
    for (int kp = 0; kp < 32; ++kp) w1p[kp] = Wu[(size_t)g1 * 64 + kp];

    for (int idx = tid; idx < 32 * 512; idx += 256) {
        int g = idx & 511, kp = idx >> 9;
        wsm2[kp * 512 + g] = Wu[(size_t)g * 64 + 32 + kp];
    }

    float c = 0.f;
    if (tid < 128) {
        hsm[tid] = h0[b * 128 + tid];
        c = c0[b * 128 + tid];
    }
    __syncthreads();

    const float* xgp = g_xg + (size_t)b * 2048 * 512;
    float xc0 = xgp[g0];
    float xc1 = xgp[g1];
    const ulonglong2* hu = (const ulonglong2*)hsm;

    for (int t = 0; t < 2048; ++t) {
        // prefetch next step's xg early (hidden under the FMA chain)
        int tn = (t < 2047) ? (t + 1) : 2047;
        float xn0 = xgp[(size_t)tn * 512 + g0];
        float xn1 = xgp[(size_t)tn * 512 + g1];

        ULL a0 = 0ULL, a1 = 0ULL;
        #pragma unroll
        for (int kq = 0; kq < 16; ++kq) {          // k in [0,64): register weights
            ulonglong2 hp = hu[kq];
            fma2(a0, w0p[2 * kq],     hp.x);
            fma2(a0, w0p[2 * kq + 1], hp.y);
            fma2(a1, w1p[2 * kq],     hp.x);
            fma2(a1, w1p[2 * kq + 1], hp.y);
        }
        #pragma unroll
        for (int kq = 0; kq < 16; ++kq) {          // k in [64,128): smem weights
            ulonglong2 hp = hu[16 + kq];
            fma2(a0, wsm2[(2 * kq) * 512 + g0],     hp.x);
            fma2(a0, wsm2[(2 * kq + 1) * 512 + g0], hp.y);
            fma2(a1, wsm2[(2 * kq) * 512 + g1],     hp.x);
            fma2(a1, wsm2[(2 * kq + 1) * 512 + g1], hp.y);
        }
        float2 u0 = unpk(a0), u1 = unpk(a1);
        gsm[g0] = u0.x + u0.y + xc0;   // bias already folded into xg
        gsm[g1] = u1.x + u1.y + xc1;
        __syncthreads();

        if (tid < 128) {
            float gi = gsm[tid];
            float gf = gsm[128 + tid];
            float gg = gsm[256 + tid];
            float go = gsm[384 + tid];
            float si = __fdividef(1.f, 1.f + __expf(-gi));
            float sf = __fdividef(1.f, 1.f + __expf(-gf));
            float so = __fdividef(1.f, 1.f + __expf(-go));
            float tg = 1.f - __fdividef(2.f, __expf(2.f * gg) + 1.f);
            c = sf * c + si * tg;
            float th = 1.f - __fdividef(2.f, __expf(2.f * c) + 1.f);
            hsm[tid] = so * th;
        }
        xc0 = xn0; xc1 = xn1;
        __syncthreads();
    }

    // fused head: out[b] = W_cls . relu(W_out . hT + b_out) + b_cls
    if (tid < 128) {
        float acc = b_out[tid];
        const float* wr = W_out + (size_t)tid * 128;
        #pragma unroll 8
        for (int k = 0; k < 128; ++k) acc += wr[k] * hsm[k];
        gsm[tid] = fmaxf(acc, 0.f) * W_cls[tid];
    }
    __syncthreads();
    for (int s = 64; s > 0; s >>= 1) {
        if (tid < s) gsm[tid] += gsm[tid + s];
        __syncthreads();
    }
    if (tid == 0) out[b] = gsm[0] + b_cls[0];
}

// ---------------------------------------------------------------------------
extern "C" void kernel_launch(void* const* d_in, const int* in_sizes, int n_in,
                              void* d_out, int out_size) {
    (void)in_sizes; (void)n_in; (void)out_size;
    const float* x     = (const float*)d_in[0];
    const float* h0    = (const float*)d_in[1];
    const float* c0    = (const float*)d_in[2];
    const float* W_ih  = (const float*)d_in[3];
    const float* W_hh  = (const float*)d_in[4];
    const float* b_ih  = (const float*)d_in[5];
    const float* b_hh  = (const float*)d_in[6];
    const float* W_out = (const float*)d_in[7];
    const float* b_out = (const float*)d_in[8];
    const float* W_cls = (const float*)d_in[9];
    const float* b_cls = (const float*)d_in[10];
    float* out = (float*)d_out;

    const int smA = 256 * 129 * 4 + 128 * 32 * 16;       // 132096 + 65536 = 197632
    const int smB = 32 * 512 * 8 + (128 + 512) * 4;      // 131072 + 2560  = 133632
    cudaFuncSetAttribute(xg_kernel, cudaFuncAttributeMaxDynamicSharedMemorySize, smA);
    cudaFuncSetAttribute(lstm_rec_kernel, cudaFuncAttributeMaxDynamicSharedMemorySize, smB);

    xg_kernel<<<dim3(16, 2, 128), 512, smA>>>(x, W_ih, b_ih, b_hh);
    lstm_rec_kernel<<<128, 256, smB>>>(W_hh, h0, c0, W_out, b_out, W_cls, b_cls, out);
}

// round 3
// speedup vs baseline: 1.1571x; 1.1571x over previous
#include <cuda_runtime.h>
#include <cstddef>

typedef unsigned long long ULL;

// 512 MB scratch for precomputed input-gate projections xg[b][t][g]
__device__ float g_xg[(size_t)128 * 2048 * 512];

__device__ __forceinline__ void fma2(ULL &acc, ULL a, ULL b) {
    asm("fma.rn.f32x2 %0, %1, %2, %0;" : "+l"(acc) : "l"(a), "l"(b));
}
__device__ __forceinline__ ULL dup2(float w) {
    ULL r; asm("mov.b64 %0, {%1, %1};" : "=l"(r) : "f"(w)); return r;
}
__device__ __forceinline__ float2 unpk(ULL u) {
    float2 v; asm("mov.b64 {%0, %1}, %2;" : "=f"(v.x), "=f"(v.y) : "l"(u)); return v;
}
__device__ __forceinline__ float ex2f(float x) {
    float r; asm("ex2.approx.f32 %0, %1;" : "=f"(r) : "f"(x)); return r;
}
__device__ __forceinline__ float rcpf(float x) {
    float r; asm("rcp.approx.f32 %0, %1;" : "=f"(r) : "f"(x)); return r;
}
__device__ __forceinline__ float sigmoidf(float x) {
    return rcpf(1.f + ex2f(-1.4426950408889634f * x));
}
__device__ __forceinline__ float tanh_f(float x) {
    // 1 - 2/(e^{2x}+1); saturates correctly at +-inf via ex2/rcp
    return 1.f - 2.f * rcpf(1.f + ex2f(2.8853900817779268f * x));
}

// ---------------------------------------------------------------------------
// Phase 1: xg[b][t][g] = sum_i x[b,0,i,t] * W_ih[g,i] + (b_ih[g] + b_hh[g])
// Grid: (16 t-tiles, 2 gate-halves, 128 batch), 512 threads.
// ---------------------------------------------------------------------------
__global__ __launch_bounds__(512, 1)
void xg_kernel(const float* __restrict__ x, const float* __restrict__ W_ih,
               const float* __restrict__ b_ih, const float* __restrict__ b_hh)
{
    extern __shared__ float sm[];
    float* wsm = sm;                               // 256*129 floats = 132096 B
    float4* xs4 = (float4*)(sm + 256 * 129);       // 128*32 float4 = 65536 B

    const int tid   = threadIdx.x;
    const int b     = blockIdx.z;
    const int gBase = blockIdx.y * 256;
    const int t0    = blockIdx.x * 128;

    for (int idx = tid; idx < 256 * 128; idx += 512) {
        int i = idx & 127, g = idx >> 7;
        wsm[g * 129 + i] = W_ih[(size_t)(gBase + g) * 128 + i];
    }
    const float4* x4 = (const float4*)x;
    size_t xbase = (size_t)b * 65536 + (size_t)(t0 >> 2);
    for (int idx = tid; idx < 128 * 32; idx += 512) {
        int t4 = idx & 31, i = idx >> 5;
        xs4[i * 32 + t4] = x4[xbase + (size_t)i * 512 + t4];
    }
    __syncthreads();

    const int gG = tid & 31;
    const int tG = tid >> 5;

    ULL acc[4][8];
    #pragma unroll
    for (int p = 0; p < 4; ++p)
        #pragma unroll
        for (int j = 0; j < 8; ++j) acc[p][j] = 0ULL;

    const ulonglong2* xu2 = (const ulonglong2*)xs4;

    #pragma unroll 4
    for (int k = 0; k < 128; ++k) {
        ulonglong2 xa = xu2[k * 32 + tG * 2];
        ulonglong2 xb = xu2[k * 32 + tG * 2 + 1];
        #pragma unroll
        for (int j = 0; j < 8; ++j) {
            ULL wd = dup2(wsm[(gG + 32 * j) * 129 + k]);
            fma2(acc[0][j], wd, xa.x);
            fma2(acc[1][j], wd, xa.y);
            fma2(acc[2][j], wd, xb.x);
            fma2(acc[3][j], wd, xb.y);
        }
    }

    float bv[8];
    #pragma unroll
    for (int j = 0; j < 8; ++j) {
        int g = gBase + gG + 32 * j;
        bv[j] = b_ih[g] + b_hh[g];
    }

    #pragma unroll
    for (int p = 0; p < 4; ++p) {
        #pragma unroll
        for (int j = 0; j < 8; ++j) {
            float2 v = unpk(acc[p][j]);
            size_t r0 = ((size_t)b * 2048 + (size_t)(t0 + tG * 8 + 2 * p)) * 512
                        + gBase + gG + 32 * j;
            g_xg[r0]       = v.x + bv[j];
            g_xg[r0 + 512] = v.y + bv[j];
        }
    }
}

// ---------------------------------------------------------------------------
// Phase 2: persistent recurrence. 1 CTA per sample, 256 threads.
// Thread tid owns gate rows g0=tid (i/f) and g1=tid+256 (g/o).
// Weights: g0 all 64 k-pairs in regs, g1 pairs 0..31 in regs,
//          g1 pairs 32..63 in smem [32][256] (64KB/step -> ~512 crossbar cyc,
//          overlapping the 512-cyc fma2 issue floor).
// Gate activations computed in the 512-wide phase (warp-uniform select);
// serial tail is just c/h update with one tanh.
// ---------------------------------------------------------------------------
__global__ __launch_bounds__(256, 1)
void lstm_rec_kernel(const float* __restrict__ W_hh,
                     const float* __restrict__ h0, const float* __restrict__ c0,
                     const float* __restrict__ W_out, const float* __restrict__ b_out,
                     const float* __restrict__ W_cls, const float* __restrict__ b_cls,
                     float* __restrict__ out)
{
    extern __shared__ ULL smB[];
    ULL*   wsm = smB;                        // [32 kp][256 rows(g>=256)] = 65536 B
    float* hsm = (float*)(wsm + 32 * 256);   // 128 floats
    float* gsm = hsm + 128;                  // 512 floats

    const int tid = threadIdx.x;
    const int b   = blockIdx.x;
    const int g0  = tid;
    const int g1  = tid + 256;

    const ULL* Wu = (const ULL*)W_hh;  // [512 gates][64 k-pairs]

    // register-resident weights: g0 full row (64 pairs), g1 first half (32 pairs)
    ULL w0[64], w1[32];
    #pragma unroll
    for (int kp = 0; kp < 64; ++kp) w0[kp] = Wu[(size_t)g0 * 64 + kp];
    #pragma unroll
    for (int kp = 0; kp < 32; ++kp) w1[kp] = Wu[(size_t)g1 * 64 + kp];

    // smem: g1 rows, pairs 32..63, layout [kp][row] for conflict-free reads
    for (int idx = tid; idx < 32 * 256; idx += 256) {
        int r = idx & 255, kp = idx >> 8;
        wsm[kp * 256 + r] = Wu[(size_t)(256 + r) * 64 + 32 + kp];
    }

    float c = 0.f;
    if (tid < 128) {
        hsm[tid] = h0[b * 128 + tid];
        c = c0[b * 128 + tid];
    }
    __syncthreads();

    const float* xgp = g_xg + (size_t)b * 2048 * 512;
    float xc0 = xgp[g0];
    float xc1 = xgp[g1];
    const ulonglong2* hu = (const ulonglong2*)hsm;
    const bool lower = (tid < 128);   // warp-uniform

    for (int t = 0; t < 2048; ++t) {
        int tn = (t < 2047) ? (t + 1) : 2047;
        float xn0 = xgp[(size_t)tn * 512 + g0];
        float xn1 = xgp[(size_t)tn * 512 + g1];

        ULL a0x = 0ULL, a0y = 0ULL, a1x = 0ULL, a1y = 0ULL;
        #pragma unroll
        for (int kq = 0; kq < 16; ++kq) {            // k in [0,64): all-register
            ulonglong2 hp = hu[kq];
            fma2(a0x, w0[2 * kq],     hp.x);
            fma2(a0y, w0[2 * kq + 1], hp.y);
            fma2(a1x, w1[2 * kq],     hp.x);
            fma2(a1y, w1[2 * kq + 1], hp.y);
        }
        #pragma unroll
        for (int kq = 0; kq < 16; ++kq) {            // k in [64,128): g0 reg, g1 smem
            ulonglong2 hp = hu[16 + kq];
            fma2(a0x, w0[32 + 2 * kq],     hp.x);
            fma2(a0y, w0[32 + 2 * kq + 1], hp.y);
            fma2(a1x, wsm[(2 * kq) * 256 + tid],     hp.x);
            fma2(a1y, wsm[(2 * kq + 1) * 256 + tid], hp.y);
        }
        float2 u0x = unpk(a0x), u0y = unpk(a0y);
        float2 u1x = unpk(a1x), u1y = unpk(a1y);
        float v0 = (u0x.x + u0x.y) + (u0y.x + u0y.y) + xc0;   // i or f gate
        float v1 = (u1x.x + u1x.y) + (u1y.x + u1y.y) + xc1;   // g or o gate
        gsm[g0] = sigmoidf(v0);                               // i,f: sigmoid
        gsm[g1] = lower ? tanh_f(v1) : sigmoidf(v1);          // g: tanh, o: sigmoid
        __syncthreads();

        if (lower) {
            float ai = gsm[tid];
            float af = gsm[128 + tid];
            float ag = gsm[256 + tid];
            float ao = gsm[384 + tid];
            c = af * c + ai * ag;
            hsm[tid] = ao * tanh_f(c);
        }
        xc0 = xn0; xc1 = xn1;
        __syncthreads();
    }

    // fused head: out[b] = W_cls . relu(W_out . hT + b_out) + b_cls
    if (tid < 128) {
        float acc = b_out[tid];
        const float* wr = W_out + (size_t)tid * 128;
        #pragma unroll 8
        for (int k = 0; k < 128; ++k) acc += wr[k] * hsm[k];
        gsm[tid] = fmaxf(acc, 0.f) * W_cls[tid];
    }
    __syncthreads();
    for (int s = 64; s > 0; s >>= 1) {
        if (tid < s) gsm[tid] += gsm[tid + s];
        __syncthreads();
    }
    if (tid == 0) out[b] = gsm[0] + b_cls[0];
}

// ---------------------------------------------------------------------------
extern "C" void kernel_launch(void* const* d_in, const int* in_sizes, int n_in,
                              void* d_out, int out_size) {
    (void)in_sizes; (void)n_in; (void)out_size;
    const float* x     = (const float*)d_in[0];
    const float* h0    = (const float*)d_in[1];
    const float* c0    = (const float*)d_in[2];
    const float* W_ih  = (const float*)d_in[3];
    const float* W_hh  = (const float*)d_in[4];
    const float* b_ih  = (const float*)d_in[5];
    const float* b_hh  = (const float*)d_in[6];
    const float* W_out = (const float*)d_in[7];
    const float* b_out = (const float*)d_in[8];
    const float* W_cls = (const float*)d_in[9];
    const float* b_cls = (const float*)d_in[10];
    float* out = (float*)d_out;

    const int smA = 256 * 129 * 4 + 128 * 32 * 16;       // 197632
    const int smB = 32 * 256 * 8 + (128 + 512) * 4;      // 65536 + 2560 = 68096
    cudaFuncSetAttribute(xg_kernel, cudaFuncAttributeMaxDynamicSharedMemorySize, smA);
    cudaFuncSetAttribute(lstm_rec_kernel, cudaFuncAttributeMaxDynamicSharedMemorySize, smB);

    xg_kernel<<<dim3(16, 2, 128), 512, smA>>>(x, W_ih, b_ih, b_hh);
    lstm_rec_kernel<<<128, 256, smB>>>(W_hh, h0, c0, W_out, b_out, W_cls, b_cls, out);
}